// round 11
// baseline (speedup 1.0000x reference)
#include <cuda_runtime.h>

#define FULL 0xFFFFFFFFu
typedef unsigned long long u64;

constexpr int B = 2048;
constexpr int T = 4096;
constexpr int CH = 8;              // steps per chunk
constexpr int NCHUNK = T / CH;     // 512

__device__ __forceinline__ float tanhf_a(float x){ float y; asm("tanh.approx.f32 %0,%1;":"=f"(y):"f"(x)); return y; }
__device__ __forceinline__ u64 ffma2(u64 a, u64 b, u64 c){
    u64 d; asm("fma.rn.f32x2 %0,%1,%2,%3;" : "=l"(d) : "l"(a), "l"(b), "l"(c)); return d;
}
__device__ __forceinline__ u64 fmul2(u64 a, u64 b){
    u64 d; asm("mul.rn.f32x2 %0,%1,%2;" : "=l"(d) : "l"(a), "l"(b)); return d;
}
__device__ __forceinline__ u64 fadd2(u64 a, u64 b){
    u64 d; asm("add.rn.f32x2 %0,%1,%2;" : "=l"(d) : "l"(a), "l"(b)); return d;
}
__device__ __forceinline__ u64 pack2(float lo, float hi){
    u64 d; asm("mov.b64 %0,{%1,%2};" : "=l"(d) : "f"(lo), "f"(hi)); return d;
}
__device__ __forceinline__ void unpack2(u64 v, float& lo, float& hi){
    asm("mov.b64 {%0,%1},%2;" : "=f"(lo), "=f"(hi) : "l"(v));
}
__device__ __forceinline__ u64 dup2(float v){ return pack2(v, v); }
__device__ __forceinline__ void pbar(int id){ asm volatile("bar.sync %0, 64;" :: "r"(id) : "memory"); }

// Producer/consumer layer split, LOAD-BALANCED. 256-thread blocks = 4 pairs.
// Pair k: A = wid k (SMSP k), B = wid k+4 (same SMSP) -> 2 warps/SMSP.
// Each pair owns 4 batches; lane = (group = lane>>3, unit u = lane&7);
// each lane computes all 4 gates of its unit, pair-packed (i,f),(g,o) f32x2.
// A: layer-0 recurrence + PARTIAL L1-input matvec (b1 + sum_{k=0..5}) -> ring,
//    plus dup-packed h1[6],h1[7] -> ring (lanes u==6,7).
// B: finishes L1 input (k=6,7), layer-1 recurrence, activations, head, store.
//    B fetches next step's partial/h67 one step ahead (LDS off the chain).
// Double-buffered 8-step chunks, one named barrier per chunk; B lags 1 chunk.
// Activations via MUFU.TANH: sigmoid(z)=0.5*tanh(0.5z)+0.5, 0.5 pre-folded.
__global__ void __launch_bounds__(256, 1)
lstm2_kernel(const float* __restrict__ x,
             const float* __restrict__ Wih0, const float* __restrict__ Whh0,
             const float* __restrict__ bih0, const float* __restrict__ bhh0,
             const float* __restrict__ Wih1, const float* __restrict__ Whh1,
             const float* __restrict__ bih1, const float* __restrict__ bhh1,
             const float* __restrict__ Wlin, const float* __restrict__ blin,
             float* __restrict__ out)
{
    __shared__ __align__(16) u64 ring_p[4][2][CH][32][2];  // partials, 32 KB
    __shared__ __align__(16) u64 ring_h[4][2][CH][4][2];   // h1[6],h1[7] dup, 4 KB

    const int tid  = threadIdx.x;
    const int lane = tid & 31;
    const int wid  = tid >> 5;
    const bool isA = (wid < 4);
    const int pair = wid & 3;
    const int u    = lane & 7;
    const int grp  = lane >> 3;
    const int base = lane & 24;
    const int bb   = blockIdx.x * 16 + pair * 4;    // first batch of this pair
    const int barid = 1 + pair;

    const float Hs = 0.5f;

    if (isA) {
        // ============ producer: layer 0 + L1-input partial (k=0..5) ============
        u64 whh0_if[8], whh0_go[8], wih1_if[6], wih1_go[6];
#pragma unroll
        for (int k = 0; k < 8; k++) {
            whh0_if[k] = pack2(Hs*Whh0[u*8+k],      Hs*Whh0[(8+u)*8+k]);
            whh0_go[k] = pack2(Whh0[(16+u)*8+k],    Hs*Whh0[(24+u)*8+k]);
        }
#pragma unroll
        for (int k = 0; k < 6; k++) {
            wih1_if[k] = pack2(Hs*Wih1[u*8+k],      Hs*Wih1[(8+u)*8+k]);
            wih1_go[k] = pack2(Wih1[(16+u)*8+k],    Hs*Wih1[(24+u)*8+k]);
        }
        const u64 wx_if0 = pack2(Hs*Wih0[u],    Hs*Wih0[8+u]);
        const u64 wx_go0 = pack2(Wih0[16+u],    Hs*Wih0[24+u]);
        const u64 b_if0  = pack2(Hs*(bih0[u]+bhh0[u]),      Hs*(bih0[8+u]+bhh0[8+u]));
        const u64 b_go0  = pack2((bih0[16+u]+bhh0[16+u]),   Hs*(bih0[24+u]+bhh0[24+u]));
        const u64 b_if1  = pack2(Hs*(bih1[u]+bhh1[u]),      Hs*(bih1[8+u]+bhh1[8+u]));
        const u64 b_go1  = pack2((bih1[16+u]+bhh1[16+u]),   Hs*(bih1[24+u]+bhh1[24+u]));

        u64 h1x[8];
#pragma unroll
        for (int k = 0; k < 8; k++) h1x[k] = 0ull;
        float c1 = 0.f;

        // lane l holds x[bb + grp][c*CH + u]
        const float* xrow = x + (size_t)(bb + grp) * T + u;
        float xcur = xrow[0];

        for (int c = 0; c < NCHUNK; c++) {
            float xnext = 0.f;
            if (c + 1 < NCHUNK) xnext = xrow[(c + 1) * CH];

#pragma unroll
            for (int s = 0; s < CH; s++) {
                const float xt = __shfl_sync(FULL, xcur, base + s);
                // ---- L0 matvec (split 4+4 chains) ----
                u64 xd   = dup2(xt);
                u64 aif0 = ffma2(wx_if0, xd, b_if0);
                u64 ago0 = ffma2(wx_go0, xd, b_go0);
                u64 aif1 = fmul2(whh0_if[4], h1x[4]);
                u64 ago1 = fmul2(whh0_go[4], h1x[4]);
#pragma unroll
                for (int k = 0; k < 4; k++) {
                    aif0 = ffma2(whh0_if[k], h1x[k], aif0);
                    ago0 = ffma2(whh0_go[k], h1x[k], ago0);
                }
#pragma unroll
                for (int k = 5; k < 8; k++) {
                    aif1 = ffma2(whh0_if[k], h1x[k], aif1);
                    ago1 = ffma2(whh0_go[k], h1x[k], ago1);
                }
                u64 aif = fadd2(aif0, aif1);
                u64 ago = fadd2(ago0, ago1);
                float zi, zf, zg, zo;
                unpack2(aif, zi, zf);
                unpack2(ago, zg, zo);
                float iv = fmaf(0.5f, tanhf_a(zi), 0.5f);
                float fv = fmaf(0.5f, tanhf_a(zf), 0.5f);
                float gv = tanhf_a(zg);
                float ov = fmaf(0.5f, tanhf_a(zo), 0.5f);
                c1 = fmaf(fv, c1, iv * gv);
                float h = ov * tanhf_a(c1);
                // publish h1[6], h1[7] dup-packed (off-chain, before redist)
                if (u >= 6)
                    ring_h[pair][c & 1][s][grp][u - 6] = dup2(h);
                // ---- redistribute h1 (chain-critical: shfl) ----
#pragma unroll
                for (int k = 0; k < 8; k++)
                    h1x[k] = dup2(__shfl_sync(FULL, h, base + k));
                // ---- L1 input partial, k=0..5 (off-chain, 6-deep) ----
                u64 rif = ffma2(wih1_if[0], h1x[0], b_if1);
                u64 rgo = ffma2(wih1_go[0], h1x[0], b_go1);
#pragma unroll
                for (int k = 1; k < 6; k++) {
                    rif = ffma2(wih1_if[k], h1x[k], rif);
                    rgo = ffma2(wih1_go[k], h1x[k], rgo);
                }
                *(ulonglong2*)&ring_p[pair][c & 1][s][lane][0] = make_ulonglong2(rif, rgo);
            }
            xcur = xnext;
            pbar(barid);
        }
        pbar(barid);                     // cover B's final chunk
    } else {
        // ========= consumer: L1 input tail (k=6,7) + layer-1 + head =========
        u64 whh1_if[8], whh1_go[8];
#pragma unroll
        for (int k = 0; k < 8; k++) {
            whh1_if[k] = pack2(Hs*Whh1[u*8+k],      Hs*Whh1[(8+u)*8+k]);
            whh1_go[k] = pack2(Whh1[(16+u)*8+k],    Hs*Whh1[(24+u)*8+k]);
        }
        const u64 wih1_if6 = pack2(Hs*Wih1[u*8+6],     Hs*Wih1[(8+u)*8+6]);
        const u64 wih1_go6 = pack2(Wih1[(16+u)*8+6],   Hs*Wih1[(24+u)*8+6]);
        const u64 wih1_if7 = pack2(Hs*Wih1[u*8+7],     Hs*Wih1[(8+u)*8+7]);
        const u64 wih1_go7 = pack2(Wih1[(16+u)*8+7],   Hs*Wih1[(24+u)*8+7]);
        const float wlu = Wlin[u];
        const float blv = blin[0];

        u64 h2x[8];
#pragma unroll
        for (int k = 0; k < 8; k++) h2x[k] = 0ull;
        float c2 = 0.f, pbuf = 0.f;

        float* ob = out + (size_t)(bb + grp) * T;

        pbar(barid);                     // wait for chunk 0
        for (int c = 0; c < NCHUNK; c++) {
            const int buf = c & 1;
            // step-0 data for this chunk
            ulonglong2 part = *(const ulonglong2*)&ring_p[pair][buf][0][lane][0];
            ulonglong2 h67  = *(const ulonglong2*)&ring_h[pair][buf][0][grp][0];
#pragma unroll
            for (int s = 0; s < CH; s++) {
                // prefetch next step (off-chain; hidden under this step's math)
                ulonglong2 part_n, h67_n;
                if (s + 1 < CH) {
                    part_n = *(const ulonglong2*)&ring_p[pair][buf][s + 1][lane][0];
                    h67_n  = *(const ulonglong2*)&ring_h[pair][buf][s + 1][grp][0];
                }
                // ---- finish L1 input (k=6,7) + Whh1*h2 matvec (4+4 chains) ----
                u64 bif0 = ffma2(whh1_if[0], h2x[0], part.x);
                u64 bgo0 = ffma2(whh1_go[0], h2x[0], part.y);
                u64 bif1 = fmul2(wih1_if6, h67.x);
                u64 bgo1 = fmul2(wih1_go6, h67.x);
                bif1 = ffma2(wih1_if7, h67.y, bif1);
                bgo1 = ffma2(wih1_go7, h67.y, bgo1);
#pragma unroll
                for (int k = 1; k < 4; k++) {
                    bif0 = ffma2(whh1_if[k], h2x[k], bif0);
                    bgo0 = ffma2(whh1_go[k], h2x[k], bgo0);
                }
#pragma unroll
                for (int k = 4; k < 8; k++) {
                    bif1 = ffma2(whh1_if[k], h2x[k], bif1);
                    bgo1 = ffma2(whh1_go[k], h2x[k], bgo1);
                }
                u64 aif = fadd2(bif0, bif1);
                u64 ago = fadd2(bgo0, bgo1);
                float zi, zf, zg, zo;
                unpack2(aif, zi, zf);
                unpack2(ago, zg, zo);
                float iv = fmaf(0.5f, tanhf_a(zi), 0.5f);
                float fv = fmaf(0.5f, tanhf_a(zf), 0.5f);
                float gv = tanhf_a(zg);
                float ov = fmaf(0.5f, tanhf_a(zo), 0.5f);
                c2 = fmaf(fv, c2, iv * gv);
                float h2 = ov * tanhf_a(c2);
                // ---- head: butterfly reduce within the 8-lane batch group ----
                float p = wlu * h2;
                p += __shfl_xor_sync(FULL, p, 1);
                p += __shfl_xor_sync(FULL, p, 2);
                p += __shfl_xor_sync(FULL, p, 4);
                if (u == s) pbuf = p + blv;          // bank step t in lane t&7
                // ---- redistribute h2 via shfl (no smem/syncwarp on chain) ----
#pragma unroll
                for (int k = 0; k < 8; k++)
                    h2x[k] = dup2(__shfl_sync(FULL, h2, base + k));
                part = part_n;
                h67  = h67_n;
            }
            ob[c * CH + u] = pbuf;                    // 8 banked steps -> coalesced
            pbar(barid);
        }
    }
}

extern "C" void kernel_launch(void* const* d_in, const int* in_sizes, int n_in,
                              void* d_out, int out_size)
{
    const float* x    = (const float*)d_in[0];
    const float* Wih0 = (const float*)d_in[1];
    const float* Whh0 = (const float*)d_in[2];
    const float* bih0 = (const float*)d_in[3];
    const float* bhh0 = (const float*)d_in[4];
    const float* Wih1 = (const float*)d_in[5];
    const float* Whh1 = (const float*)d_in[6];
    const float* bih1 = (const float*)d_in[7];
    const float* bhh1 = (const float*)d_in[8];
    const float* Wlin = (const float*)d_in[9];
    const float* blin = (const float*)d_in[10];
    float* out = (float*)d_out;

    // 16 batches per block (4 pairs x 4 batches); 256 threads; 128 blocks.
    const int threads = 256;
    const int blocks  = B / 16;                   // 128
    lstm2_kernel<<<blocks, threads>>>(x, Wih0, Whh0, bih0, bhh0,
                                      Wih1, Whh1, bih1, bhh1, Wlin, blin, out);
}